// round 13
// baseline (speedup 1.0000x reference)
#include <cuda_runtime.h>

#define LAYERS   8
#define WIDTH    128
#define DDIM     64
#define KNOTS    8
#define PPD      23          // 3*KNOTS-1
#define BATCH    16384
#define TB       64          // batch rows per CTA
#define NTHREADS 512
#define DGC      8           // dims per chunk (1 per warp in a group)
#define XPAD     68
#define HPAD     132
#define WQPAD    36          // 32-col quarter staging row stride
#define GBUF     (64*WQPAD)  // one group quarter buffer: 8 dims x 8 params rows
#define BI       4.0f

// shared memory layout (float offsets)
#define OFF_X0   0
#define OFF_X1   (TB*XPAD)                    // 4352
#define OFF_H    (2*TB*XPAD)                  // 8704
#define OFF_WS   (2*TB*XPAD + TB*HPAD)        // 17152
#define WSTOT    (4*GBUF)                     // 2 groups x 2 ping-pong = 9216
#define SMEM_FLOATS (OFF_WS + WSTOT)          // 26368
#define SMEM_BYTES  (SMEM_FLOATS*4)           // 105472 B -> 2 CTAs/SM

// W1 staging reuses the same WS area as 2 col-half buffers of 128 rows
#define W1BUF    (128*WQPAD)                  // 4608

// Pre-masked, degree-sorted weights (static device scratch).
__device__ float g_W1m[2*LAYERS*WIDTH*DDIM];
__device__ float g_Wom[2*LAYERS*DDIM*PPD*WIDTH + 128];
__device__ float g_b1p[2*LAYERS*WIDTH];

// ---------------------------------------------------------------------------
__device__ __forceinline__ unsigned long long ffma2(unsigned long long a,
                                                    unsigned long long b,
                                                    unsigned long long c)
{
    unsigned long long d;
    asm("fma.rn.f32x2 %0, %1, %2, %3;" : "=l"(d) : "l"(a), "l"(b), "l"(c));
    return d;
}
__device__ __forceinline__ float2 unpack2(unsigned long long v)
{
    float2 r;
    asm("mov.b64 {%0, %1}, %2;" : "=f"(r.x), "=f"(r.y) : "l"(v));
    return r;
}
// group barrier: named barrier (1+g), 256 threads
__device__ __forceinline__ void barg(int bid)
{
    asm volatile("bar.sync %0, %1;" :: "r"(bid), "r"(256) : "memory");
}

// softplus = max(v,0) + log(1 + exp(-|v|))
__device__ __forceinline__ float softplus_fast(float v)
{
    float t = __expf(-fabsf(v));
    return fmaxf(v, 0.f) + __logf(1.f + t);
}

// ---------------------------------------------------------------------------
// Degree-sorted hidden permutation.
// ---------------------------------------------------------------------------
__host__ __device__ __forceinline__ int sdeg(int j) { return (j < 6) ? (j/3) : ((j-2)>>1); }
__host__ __device__ __forceinline__ int permf(int j)
{
    if (j < 3)  return (j == 0) ? 0 : (j == 1 ? 63 : 126);
    if (j < 6)  return (j == 3) ? 1 : (j == 4 ? 64 : 127);
    int v = (j - 2) >> 1;
    return ((j & 1) == 0) ? v : v + 63;
}
__device__ __forceinline__ int kmax_of(int d)
{
    int n = (d == 0) ? 0 : (d == 1 ? 3 : 2*d + 2);
    n = (n + 7) & ~7;
    return n > 128 ? 128 : n;
}

// ---------------------------------------------------------------------------
// Prep: mask + permute weights once per launch.
// ---------------------------------------------------------------------------
__global__ void prep_kernel(const float* __restrict__ fW1, const float* __restrict__ fWo,
                            const float* __restrict__ gW1, const float* __restrict__ gWo,
                            const float* __restrict__ fb1, const float* __restrict__ gb1)
{
    const int N1 = LAYERS*WIDTH*DDIM;
    const int N2 = LAYERS*DDIM*PPD*WIDTH;
    const int stride = gridDim.x * blockDim.x;
    const int t0 = blockIdx.x*blockDim.x + threadIdx.x;

    for (int i = t0; i < 2*N1; i += stride) {
        int fl = i / N1, j = i - fl*N1;
        int row = (j >> 6) & (WIDTH-1);
        int c = j & (DDIM-1);
        int l = j >> 13;
        const float* s = fl ? gW1 : fW1;
        int src = permf(row);
        g_W1m[i] = (c <= sdeg(row)) ? s[l*WIDTH*DDIM + src*DDIM + c] : 0.f;
    }
    for (int i = t0; i < 2*N2; i += stride) {
        int fl = i / N2, j = i - fl*N2;
        int col = j & (WIDTH-1);
        int o = (j >> 7) % (DDIM*PPD);
        int l = j / (DDIM*PPD*WIDTH);
        int d = o / PPD;
        const float* s = fl ? gWo : fWo;
        int src = permf(col);
        g_Wom[i] = (sdeg(col) < d) ? s[l*(DDIM*PPD)*WIDTH + o*WIDTH + src] : 0.f;
    }
    if (t0 < 128) g_Wom[2*N2 + t0] = 0.f;
    for (int i = t0; i < 2*LAYERS*WIDTH; i += stride) {
        int fl = i / (LAYERS*WIDTH), j = i - fl*(LAYERS*WIDTH);
        int l = j >> 7, w = j & (WIDTH-1);
        const float* s = fl ? gb1 : fb1;
        g_b1p[i] = s[l*WIDTH + permf(w)];
    }
}

// ---------------------------------------------------------------------------
// Group quarter stage: 8 dims x 8 params x 32 cols -> buf.  Predicated on
// each dim actually needing this quarter (kmax > 32q).
// ---------------------------------------------------------------------------
__device__ __forceinline__ void stage_q8(
    float* buf, const float* __restrict__ Wol, int d0, int pbase, int q, int tg)
{
#pragma unroll
    for (int it = 0; it < 2; it++) {
        int i = tg + it*256;            // 0..511 -> 512 float4s
        int rr = i >> 3, c4 = i & 7;    // rr: 0..63 (dd*8+pp)
        int dd = rr >> 3, pp = rr & 7;
        if (kmax_of(d0 + dd) > 32*q) {
            float4 v = *(const float4*)&Wol[((d0+dd)*PPD + pbase + pp)*WIDTH + q*32 + c4*4];
            *(float4*)&buf[rr*WQPAD + c4*4] = v;
        }
    }
}

// ---------------------------------------------------------------------------
// GEMM2 pass (group-scoped): PCNT params x 2 rows over this warp's dim
// K-prefix.  Group ping-pong staging + named-barrier sync.
// ---------------------------------------------------------------------------
template<int PBASE, int PCNT>
__device__ __forceinline__ void gemm2_pass(
    float* sm, float* gws, const float* __restrict__ Wol, const float* __restrict__ bo,
    int d0, int wl, int lane, int tg, int bid, int nq, int kmax, float out[2][8])
{
    unsigned long long acc[2][PCNT];
#pragma unroll
    for (int ri = 0; ri < 2; ri++)
#pragma unroll
        for (int p = 0; p < PCNT; p++) acc[ri][p] = 0ull;

    stage_q8(gws, Wol, d0, PBASE, 0, tg);
    barg(bid);

    for (int q = 0; q < nq; q++) {
        int bound = kmax - 32*q;                    // warp-uniform
        bound = bound < 0 ? 0 : (bound > 32 ? 32 : bound);
        const float* hbase = &sm[OFF_H + q*32];
        const float* wsp   = &gws[(q & 1)*GBUF + (wl*8)*WQPAD];
#pragma unroll 4
        for (int k4 = 0; k4 < (bound >> 2); k4++) {
            ulonglong2 h0 = *(const ulonglong2*)&hbase[(lane     )*HPAD + k4*4];
            ulonglong2 h1 = *(const ulonglong2*)&hbase[(lane + 32)*HPAD + k4*4];
#pragma unroll
            for (int p = 0; p < PCNT; p++) {
                ulonglong2 wv = *(const ulonglong2*)&wsp[p*WQPAD + k4*4];
                acc[0][p] = ffma2(h0.x, wv.x, acc[0][p]);
                acc[0][p] = ffma2(h0.y, wv.y, acc[0][p]);
                acc[1][p] = ffma2(h1.x, wv.x, acc[1][p]);
                acc[1][p] = ffma2(h1.y, wv.y, acc[1][p]);
            }
        }
        if (q + 1 < nq)
            stage_q8(&gws[((q+1) & 1)*GBUF], Wol, d0, PBASE, q + 1, tg);
        barg(bid);
    }

#pragma unroll
    for (int ri = 0; ri < 2; ri++)
#pragma unroll
        for (int p = 0; p < PCNT; p++) {
            float2 u = unpack2(acc[ri][p]);
            out[ri][p] = u.x + u.y + bo[PBASE + p];
        }
}

// ---------------------------------------------------------------------------
// Main kernel: one CTA (512 thr) = 64 rows through all 8 layers; 2 CTAs/SM.
// Two independent 8-warp groups (named barriers) split the 8 dim-chunks:
// group A {0,3,4,7}, group B {1,2,5,6} (work-balanced).  GEMM1 balanced
// quads, full-CTA.  Spline streamed in 3 phases; MUFU-minimized.
// ---------------------------------------------------------------------------
__global__ __launch_bounds__(NTHREADS, 2)
void maf_kernel(const float* __restrict__ xin_f, const float* __restrict__ xin_g,
                const float* __restrict__ f_bout, const float* __restrict__ g_bout,
                float* __restrict__ out)
{
    extern __shared__ float sm[];
    const int tid   = threadIdx.x;
    const int flow  = blockIdx.y;
    const int row0  = blockIdx.x * TB;
    const int warpi = tid >> 5;    // 0..15
    const int lane  = tid & 31;
    const int grp   = warpi >> 3;  // 0/1
    const int wl    = warpi & 7;   // warp-local dim slot within chunk
    const int tg    = tid & 255;   // group-local thread id
    const int bid   = 1 + grp;     // named barrier id
    float* gws = &sm[OFF_WS + grp*2*GBUF];
    const int chmap = grp ? 0x6521 : 0x7430;   // packed chunk lists

    const float* xin   = flow ? xin_g  : xin_f;
    const float* boutg = flow ? g_bout : f_bout;
    const float* b1p   = g_b1p + flow * (LAYERS*WIDTH);
    const float* W1m   = g_W1m + flow * (LAYERS*WIDTH*DDIM);
    const float* Wom   = g_Wom + flow * (LAYERS*DDIM*PPD*WIDTH);

    for (int i = tid; i < TB*DDIM; i += NTHREADS) {
        int r = i >> 6, d = i & 63;
        sm[OFF_X0 + r*XPAD + d] = xin[row0*DDIM + i];
    }

    const float C1 = 8.0f / 1.01f;
    const float CADJ = 0.00125f;

    float ldacc[2] = {0.f, 0.f};
    int cur = OFF_X0, nxt = OFF_X1;

    __syncthreads();

    for (int layer = 0; layer < LAYERS; layer++) {
        // ---- W1 stage: 128 rows x 64 cols, 2 col-half buffers (full CTA)
        const float* W1l = W1m + layer*WIDTH*DDIM;
#pragma unroll
        for (int it = 0; it < 4; it++) {
            int i = tid + it*NTHREADS;
            int rr = i >> 4, c4 = i & 15;
            float4 v = *(const float4*)&W1l[rr*DDIM + c4*4];
            *(float4*)&sm[OFF_WS + (c4 >> 3)*W1BUF + rr*WQPAD + (c4 & 7)*4] = v;
        }
        __syncthreads();

        // ---- GEMM1 (balanced): warp w -> quads {w, 31-w}; rows {lane,lane+32}
        {
            const int qa = warpi, qb = 31 - warpi;
            const int ka  = (qa + 2) >> 1;
            const int kb4 = (qb + 2) >> 1;

            unsigned long long acc[2][8];
#pragma unroll
            for (int ri = 0; ri < 2; ri++)
#pragma unroll
                for (int p = 0; p < 8; p++) acc[ri][p] = 0ull;

            const float* wa  = &sm[OFF_WS + (4*qa)*WQPAD];
            const float* wb0 = &sm[OFF_WS + (4*qb)*WQPAD];
            const float* wb1 = &sm[OFF_WS + W1BUF + (4*qb)*WQPAD];

#pragma unroll 2
            for (int kk = 0; kk < ka; kk++) {
                ulonglong2 x0 = *(const ulonglong2*)&sm[cur + (lane     )*XPAD + kk*4];
                ulonglong2 x1 = *(const ulonglong2*)&sm[cur + (lane + 32)*XPAD + kk*4];
#pragma unroll
                for (int p = 0; p < 4; p++) {
                    ulonglong2 wv = *(const ulonglong2*)&wa[p*WQPAD + kk*4];
                    acc[0][p] = ffma2(x0.x, wv.x, acc[0][p]);
                    acc[0][p] = ffma2(x0.y, wv.y, acc[0][p]);
                    acc[1][p] = ffma2(x1.x, wv.x, acc[1][p]);
                    acc[1][p] = ffma2(x1.y, wv.y, acc[1][p]);
                }
            }
#pragma unroll 2
            for (int kk = 0; kk < 8; kk++) {
                ulonglong2 x0 = *(const ulonglong2*)&sm[cur + (lane     )*XPAD + kk*4];
                ulonglong2 x1 = *(const ulonglong2*)&sm[cur + (lane + 32)*XPAD + kk*4];
#pragma unroll
                for (int p = 0; p < 4; p++) {
                    ulonglong2 wv = *(const ulonglong2*)&wb0[p*WQPAD + kk*4];
                    acc[0][4+p] = ffma2(x0.x, wv.x, acc[0][4+p]);
                    acc[0][4+p] = ffma2(x0.y, wv.y, acc[0][4+p]);
                    acc[1][4+p] = ffma2(x1.x, wv.x, acc[1][4+p]);
                    acc[1][4+p] = ffma2(x1.y, wv.y, acc[1][4+p]);
                }
            }
#pragma unroll 2
            for (int kk = 8; kk < kb4; kk++) {
                int kl = kk - 8;
                ulonglong2 x0 = *(const ulonglong2*)&sm[cur + (lane     )*XPAD + kk*4];
                ulonglong2 x1 = *(const ulonglong2*)&sm[cur + (lane + 32)*XPAD + kk*4];
#pragma unroll
                for (int p = 0; p < 4; p++) {
                    ulonglong2 wv = *(const ulonglong2*)&wb1[p*WQPAD + kl*4];
                    acc[0][4+p] = ffma2(x0.x, wv.x, acc[0][4+p]);
                    acc[0][4+p] = ffma2(x0.y, wv.y, acc[0][4+p]);
                    acc[1][4+p] = ffma2(x1.x, wv.x, acc[1][4+p]);
                    acc[1][4+p] = ffma2(x1.y, wv.y, acc[1][4+p]);
                }
            }

            float4 ba = *(const float4*)&b1p[layer*WIDTH + 4*qa];
            float4 bb = *(const float4*)&b1p[layer*WIDTH + 4*qb];
            float bav[4] = {ba.x, ba.y, ba.z, ba.w};
            float bbv[4] = {bb.x, bb.y, bb.z, bb.w};
#pragma unroll
            for (int ri = 0; ri < 2; ri++) {
                int r = lane + 32*ri;
                float ha[4], hb[4];
#pragma unroll
                for (int p = 0; p < 4; p++) {
                    float2 ua = unpack2(acc[ri][p]);
                    ha[p] = fmaxf(ua.x + ua.y + bav[p], 0.f);
                    float2 ub = unpack2(acc[ri][4+p]);
                    hb[p] = fmaxf(ub.x + ub.y + bbv[p], 0.f);
                }
                *(float4*)&sm[OFF_H + r*HPAD + 4*qa] = make_float4(ha[0],ha[1],ha[2],ha[3]);
                *(float4*)&sm[OFF_H + r*HPAD + 4*qb] = make_float4(hb[0],hb[1],hb[2],hb[3]);
            }
        }
        __syncthreads();   // H ready; groups now independent

        // ---- GEMM2 + streamed spline: 4 chunks of 8 dims per group ----
        for (int ci = 0; ci < 4; ci++) {
            const int c  = (chmap >> (ci*4)) & 15;
            const int d0 = c * DGC;
            const int d  = d0 + wl;
            const int kmax = kmax_of(d);                 // warp-uniform
            const int nq   = (kmax_of(d0 + 7) + 31) >> 5;  // group-chunk-uniform
            const float* Wol = Wom + layer*DDIM*PPD*WIDTH;
            const float* bo  = boutg + (layer*DDIM + d)*PPD;

            float pr[2][8];
            float st_xi[2], st_invdx[2], st_yk[2], st_dyv[2], st_sk[2];
            int   st_k[2];

            // ===== phase 1: widths =====
            gemm2_pass<0, 8>(sm, gws, Wol, bo, d0, wl, lane, tg, bid, nq, kmax, pr);
#pragma unroll
            for (int ri = 0; ri < 2; ri++) {
                float mw = pr[ri][0];
#pragma unroll
                for (int j = 1; j < 8; j++) mw = fmaxf(mw, pr[ri][j]);
                float ew[8]; float swv = 0.f;
#pragma unroll
                for (int j = 0; j < 8; j++) { ew[j] = __expf(pr[ri][j] - mw); swv += ew[j]; }
                float isc = __frcp_rn(swv) * C1;
                float cadj = CADJ * C1;

                float xraw = sm[cur + (lane + 32*ri)*XPAD + d];
                float xc = fminf(fmaxf(xraw, -BI), BI);

                float xl = -BI;
                float xk = -BI, xk1 = -BI;
                int k = 0;
#pragma unroll
                for (int j = 0; j < 8; j++) {
                    float wj = ew[j]*isc + cadj;
                    float xr2 = xl + wj;
                    if (xc >= xl) { k = j; xk = xl; xk1 = xr2; }
                    xl = xr2;
                }
                float invdx = __frcp_rn(xk1 - xk);
                st_invdx[ri] = invdx;
                st_xi[ri] = (xc - xk) * invdx;
                st_k[ri] = k;
            }

            // ===== phase 2: heights =====
            gemm2_pass<8, 8>(sm, gws, Wol, bo, d0, wl, lane, tg, bid, nq, kmax, pr);
#pragma unroll
            for (int ri = 0; ri < 2; ri++) {
                float mh = pr[ri][0];
#pragma unroll
                for (int j = 1; j < 8; j++) mh = fmaxf(mh, pr[ri][j]);
                float eh[8]; float shv = 0.f;
#pragma unroll
                for (int j = 0; j < 8; j++) { eh[j] = __expf(pr[ri][j] - mh); shv += eh[j]; }
                float isc = __frcp_rn(shv) * C1;
                float cadj = CADJ * C1;

                const int k = st_k[ri];
                float yl = -BI;
                float yk = -BI, yk1 = -BI;
#pragma unroll
                for (int j = 0; j < 8; j++) {
                    float hj = eh[j]*isc + cadj;
                    float yr2 = yl + hj;
                    if (j == k) { yk = yl; yk1 = yr2; }
                    yl = yr2;
                }
                st_yk[ri] = yk;
                st_dyv[ri] = yk1 - yk;
                st_sk[ri] = st_dyv[ri] * st_invdx[ri];
            }

            // ===== phase 3: derivatives (2 selected) =====
            gemm2_pass<16, 7>(sm, gws, Wol, bo, d0, wl, lane, tg, bid, nq, kmax, pr);
#pragma unroll
            for (int ri = 0; ri < 2; ri++) {
                const int k = st_k[ri];
                float vkm1 = 0.f, vk = 0.f;
#pragma unroll
                for (int j = 0; j < 7; j++) {
                    float v = pr[ri][j];
                    if (j == k - 1) vkm1 = v;
                    if (j == k)     vk   = v;
                }
                float dk  = (k >= 1) ? (softplus_fast(vkm1) + 0.001f) : 1.f;
                float dk1 = (k <= 6) ? (softplus_fast(vk)   + 0.001f) : 1.f;

                float xi = st_xi[ri];
                float omx = 1.f - xi;
                float xiomx = xi * omx;
                float sk = st_sk[ri];
                float den = sk + (dk1 + dk - 2.f*sk) * xiomx;
                float invden = __frcp_rn(den);
                float nume = sk*xi*xi + dk*xiomx;
                float outv = st_yk[ri] + st_dyv[ri] * nume * invden;
                float ldn = dk1*xi*xi + 2.f*sk*xiomx + dk*omx*omx;
                float ld = __logf(sk*sk*ldn*(invden*invden));

                float xraw = sm[cur + (lane + 32*ri)*XPAD + d];
                bool inside = (xraw > -BI) && (xraw < BI);
                float xo2 = inside ? outv : xraw;
                sm[nxt + (lane + 32*ri)*XPAD + (DDIM-1 - d)] = xo2;  // reversal fused
                ldacc[ri] += inside ? ld : 0.f;
            }
        }

        __syncthreads();   // both groups done; X(nxt) ready
        int t = cur; cur = nxt; nxt = t;
    }

    // ---- outputs: [xo (B*64) | ldf (B) | yo (B*64) | ldg (B)]
    const int xbase  = flow ? (BATCH*DDIM + BATCH) : 0;
    const int ldbase = flow ? (2*BATCH*DDIM + BATCH) : (BATCH*DDIM);

    for (int i = tid; i < TB*DDIM; i += NTHREADS) {
        int rr = i >> 6, dd = i & 63;
        out[xbase + row0*DDIM + i] = sm[cur + rr*XPAD + dd];
    }

    // log-det reduction: 16 dim-class partials per row (class = warpi)
    float* red = &sm[OFF_WS];
#pragma unroll
    for (int ri = 0; ri < 2; ri++)
        red[(lane + 32*ri)*16 + warpi] = ldacc[ri];
    __syncthreads();
    if (tid < TB) {
        float s = 0.f;
#pragma unroll
        for (int j = 0; j < 16; j++) s += red[tid*16 + j];
        out[ldbase + row0 + tid] = s;
    }
}

// ---------------------------------------------------------------------------
extern "C" void kernel_launch(void* const* d_in, const int* in_sizes, int n_in,
                              void* d_out, int out_size)
{
    const float* x      = (const float*)d_in[0];
    const float* y      = (const float*)d_in[1];
    const float* f_W1   = (const float*)d_in[2];
    const float* f_b1   = (const float*)d_in[3];
    const float* f_Wout = (const float*)d_in[4];
    const float* f_bout = (const float*)d_in[5];
    const float* g_W1   = (const float*)d_in[6];
    const float* g_b1   = (const float*)d_in[7];
    const float* g_Wout = (const float*)d_in[8];
    const float* g_bout = (const float*)d_in[9];
    float* out = (float*)d_out;

    cudaFuncSetAttribute(maf_kernel, cudaFuncAttributeMaxDynamicSharedMemorySize, SMEM_BYTES);

    prep_kernel<<<1024, 256>>>(f_W1, f_Wout, g_W1, g_Wout, f_b1, g_b1);

    dim3 grid(BATCH/TB, 2);
    maf_kernel<<<grid, NTHREADS, SMEM_BYTES>>>(x, y, f_bout, g_bout, out);
}